// round 5
// baseline (speedup 1.0000x reference)
#include <cuda_runtime.h>

// ContConv1dDenseSim: out[b,l,o] = sum_{j in band, i} feat[b,j,i] * kv(dt_{l,j})[i,o]
// kv = MLP(relu) on scalar dt; banded causal mask (width 30); true_ids column mask;
// row-validity l <= 6*(len-1).
//
// Refactor (exact): FW2[j,h,o] = sum_i feat[j,i]*w2[h,i*16+o]; FB2[j,o] = sum_i feat[j,i]*b2[i*16+o]
// out[l,o] = sum_{j in band} ( FB2[j,o] + sum_h relu(dt*w1_h + b1_h) * FW2[j,h,o] )
//
// R5: shave the serial skeleton — per-warp layout detection (no sync), parallel
// feat/mask loads, early lengths prefetch, FB2 balanced across h-warps, split
// accumulator dots. 3 block barriers instead of 4.

namespace cc {
constexpr int LEN     = 512;
constexpr int BSZ     = 2;
constexpr int IN_CH   = 16;
constexpr int OUT_CH  = 16;
constexpr int HID     = 8;
constexpr int BAND    = 30;                 // j in [l-29, l]
constexpr int TILE_L  = 8;
constexpr int NJMAX   = BAND - 1 + TILE_L;  // 37
constexpr int FW2_STR = HID * OUT_CH + OUT_CH; // 144; %32==16 -> conflict-free l-halves
constexpr int NTHR    = 512;
}

__global__ __launch_bounds__(512, 1)
void cc1d_fused_kernel(const float* __restrict__ times,
                       const float* __restrict__ features,
                       const int* __restrict__ lengths_i32,   // int32 or int64 layout
                       const void* __restrict__ true_ids_raw, // u8 or int32 layout
                       const float* __restrict__ w1,
                       const float* __restrict__ b1,
                       const float* __restrict__ w2,
                       const float* __restrict__ b2,
                       float* __restrict__ out)
{
    using namespace cc;
    __shared__ float feats[NJMAX * IN_CH];
    __shared__ float fw2s[NJMAX * FW2_STR];
    __shared__ float ts[NJMAX];
    __shared__ float w1s[HID], b1s[HID];
    __shared__ float partial[3 * 128];

    const int b       = blockIdx.y;
    const int l_start = blockIdx.x * TILE_L;
    const int t       = threadIdx.x;
    const int g       = t >> 7;         // work-split group 0..3
    const int m       = t & 127;
    const int h       = m >> 4;         // hidden unit (phase1) / l_local (phase2)
    const int o       = m & 15;
    const int lane    = t & 31;

    // ---- per-warp true_ids layout detection: every warp scans the same first
    // 256 bytes (L1-resident after first touch). int32-bool values are 0/1, so
    // any nonzero byte above byte-0 => 1-byte layout. No shared mem, no sync.
    unsigned int v0 = ((const unsigned int*)true_ids_raw)[lane];
    unsigned int v1 = ((const unsigned int*)true_ids_raw)[lane + 32];
    const bool byte_layout =
        __ballot_sync(0xFFFFFFFFu, ((v0 | v1) & 0xFFFFFF00u) != 0u) != 0u;

    // ---- early global prefetches (independent; overlap with everything) ----
    float w2col[IN_CH];
    #pragma unroll
    for (int i = 0; i < IN_CH; i++)
        w2col[i] = w2[h * (IN_CH * OUT_CH) + i * OUT_CH + o];
    float b2col[IN_CH];
    #pragma unroll
    for (int i = 0; i < IN_CH; i++) b2col[i] = b2[i * OUT_CH + o];

    int len_pref;  // resolve int32 vs int64 (true lengths >= 1 -> hi word 0 <=> i64)
    {
        const int w1v = __ldg(&lengths_i32[1]);
        len_pref = (w1v == 0) ? __ldg(&lengths_i32[2 * b]) : __ldg(&lengths_i32[b]);
    }

    int j0 = l_start - (BAND - 1); if (j0 < 0) j0 = 0;
    const int nj = (l_start + TILE_L - 1) - j0 + 1;   // <= NJMAX

    if (t >= 32 && t < 32 + HID) { w1s[t - 32] = w1[t - 32]; b1s[t - 32] = b1[t - 32]; }
    if (t >= 64 && t - 64 < nj)  { ts[t - 64] = times[b * LEN + j0 + (t - 64)]; }

    // feats: unconditional feature load in parallel with mask load, then select
    for (int idx = t; idx < nj * IN_CH; idx += NTHR) {
        const int jr = idx >> 4, i = idx & 15;
        const int j  = j0 + jr;
        const float fv = features[(b * LEN + j) * IN_CH + i];
        bool act;
        if (byte_layout) act = ((const unsigned char*)true_ids_raw)[b * LEN + j] != 0;
        else             act = ((const int*)true_ids_raw)[b * LEN + j] != 0;
        feats[idx] = act ? fv : 0.0f;
    }
    __syncthreads();   // feats, ts, w1s visible

    // ---- phase 1: FW2 / FB2, j-range split 4 ways; FB2 balanced over h ----
    {
        const int q = (nj + 3) >> 2;
        const int jrA = g * q;
        int jrB = jrA + q; if (jrB > nj) jrB = nj;
        for (int jr = jrA; jr < jrB; jr++) {
            const float* fj = &feats[jr * IN_CH];
            float aA = 0.0f, aB = 0.0f;
            #pragma unroll
            for (int i = 0; i < 8; i++) {
                aA = fmaf(fj[i],     w2col[i],     aA);
                aB = fmaf(fj[i + 8], w2col[i + 8], aB);
            }
            fw2s[jr * FW2_STR + h * OUT_CH + o] = aA + aB;
            if (h == (jr & 7)) {           // spread FB2 dots across warps
                float bA = 0.0f, bB = 0.0f;
                #pragma unroll
                for (int i = 0; i < 8; i++) {
                    bA = fmaf(fj[i],     b2col[i],     bA);
                    bB = fmaf(fj[i + 8], b2col[i + 8], bB);
                }
                fw2s[jr * FW2_STR + HID * OUT_CH + o] = bA + bB;
            }
        }
    }
    __syncthreads();

    // ---- phase 2: band reduction per (l, o), band split 4 ways across groups ----
    const int l  = l_start + h;      // h == l_local here
    const int lr = l - j0;
    const float tl = ts[lr];

    float w1r[HID], b1r[HID];
    #pragma unroll
    for (int k = 0; k < HID; k++) { w1r[k] = w1s[k]; b1r[k] = b1s[k]; }

    int jr_lo = lr - (BAND - 1); if (jr_lo < 0) jr_lo = 0;
    const int blen = lr - jr_lo + 1;
    const int q2 = (blen + 3) >> 2;
    const int js = jr_lo + g * q2;
    int je = js + q2; if (je > lr + 1) je = lr + 1;

    float acc0 = 0.0f, acc1 = 0.0f;
    for (int jr = js; jr < je; jr++) {
        const float dt = tl - ts[jr];
        const float* fr = &fw2s[jr * FW2_STR];
        float a0 = fr[HID * OUT_CH + o];   // FB2 term
        float a1 = 0.0f;
        #pragma unroll
        for (int k = 0; k < HID; k += 2) {
            float hv0 = fmaf(dt, w1r[k],     b1r[k]);     hv0 = hv0 > 0.0f ? hv0 : 0.0f;
            float hv1 = fmaf(dt, w1r[k + 1], b1r[k + 1]); hv1 = hv1 > 0.0f ? hv1 : 0.0f;
            a0 = fmaf(hv0, fr[k * OUT_CH + o],       a0);
            a1 = fmaf(hv1, fr[(k + 1) * OUT_CH + o], a1);
        }
        acc0 += a0; acc1 += a1;
    }
    float acc = acc0 + acc1;

    if (g > 0) partial[(g - 1) * 128 + m] = acc;
    __syncthreads();

    if (g == 0) {
        acc += partial[m] + partial[128 + m] + partial[256 + m];
        const bool valid = l <= 6 * (len_pref - 1);
        out[(b * LEN + l) * OUT_CH + o] = valid ? acc : 0.0f;
    }
}

extern "C" void kernel_launch(void* const* d_in, const int* in_sizes, int n_in,
                              void* d_out, int out_size) {
    using namespace cc;
    // dict order: times, features, lengths, true_ids, [sim_size], w1, b1, w2, b2
    const float* times    = (const float*)d_in[0];
    const float* features = (const float*)d_in[1];
    const int*   lengths  = (const int*)d_in[2];
    const void*  tids     = d_in[3];

    int base = 4;
    if (n_in >= 9 && in_sizes[4] == 1) base = 5;  // sim_size scalar occupies slot 4

    const float* w1 = (const float*)d_in[base + 0];
    const float* b1 = (const float*)d_in[base + 1];
    const float* w2 = (const float*)d_in[base + 2];
    const float* b2 = (const float*)d_in[base + 3];
    float*       out = (float*)d_out;

    dim3 grid(LEN / TILE_L, BSZ);   // 64 x 2 = 128 blocks, 1 per SM
    cc1d_fused_kernel<<<grid, NTHR>>>(times, features, lengths, tids,
                                      w1, b1, w2, b2, out);
}

// round 6
// speedup vs baseline: 1.0466x; 1.0466x over previous
#include <cuda_runtime.h>

// ContConv1dDenseSim: out[b,l,o] = sum_{j in band, i} feat[b,j,i] * kv(dt_{l,j})[i,o]
// kv = MLP(relu) on scalar dt; banded causal mask (width 30); true_ids column mask;
// row-validity l <= 6*(len-1).
//
// Refactor (exact): FW2[j,h,o] = sum_i feat[j,i]*w2[h,i*16+o]; FB2[j,o] = sum_i feat[j,i]*b2[i*16+o]
// out[l,o] = sum_{j in band} ( FB2[j,o] + sum_h relu(dt*w1_h + b1_h) * FW2[j,h,o] )
//
// R6: 1024 threads/block, 8-way split of phase-1 rows and phase-2 band.
// b2 kept in shared (not registers) to stay under the 64-reg/thread cap of
// 1024-thread blocks. 8-way partial reduction.

namespace cc {
constexpr int LEN     = 512;
constexpr int BSZ     = 2;
constexpr int IN_CH   = 16;
constexpr int OUT_CH  = 16;
constexpr int HID     = 8;
constexpr int BAND    = 30;                 // j in [l-29, l]
constexpr int TILE_L  = 8;
constexpr int NJMAX   = BAND - 1 + TILE_L;  // 37
constexpr int FW2_STR = HID * OUT_CH + OUT_CH; // 144; %32==16 -> conflict-free l-halves
constexpr int NTHR    = 1024;
constexpr int NGRP    = 8;
}

__global__ __launch_bounds__(1024, 1)
void cc1d_fused_kernel(const float* __restrict__ times,
                       const float* __restrict__ features,
                       const int* __restrict__ lengths_i32,   // int32 or int64 layout
                       const void* __restrict__ true_ids_raw, // u8 or int32 layout
                       const float* __restrict__ w1,
                       const float* __restrict__ b1,
                       const float* __restrict__ w2,
                       const float* __restrict__ b2,
                       float* __restrict__ out)
{
    using namespace cc;
    __shared__ float feats[NJMAX * IN_CH];
    __shared__ float fw2s[NJMAX * FW2_STR];
    __shared__ float ts[NJMAX];
    __shared__ float w1s[HID], b1s[HID];
    __shared__ float b2s[IN_CH * OUT_CH];      // [i*16+o]
    __shared__ float partial[(NGRP - 1) * 128];

    const int b       = blockIdx.y;
    const int l_start = blockIdx.x * TILE_L;
    const int t       = threadIdx.x;
    const int g       = t >> 7;         // work-split group 0..7
    const int m       = t & 127;
    const int h       = m >> 4;         // hidden unit (phase1) / l_local (phase2)
    const int o       = m & 15;
    const int lane    = t & 31;

    // ---- per-warp true_ids layout detection: every warp scans the same first
    // 256 bytes (L1-resident after first touch). int32-bool values are 0/1, so
    // any nonzero byte above byte-0 => 1-byte layout. No shared mem, no sync.
    unsigned int v0 = ((const unsigned int*)true_ids_raw)[lane];
    unsigned int v1 = ((const unsigned int*)true_ids_raw)[lane + 32];
    const bool byte_layout =
        __ballot_sync(0xFFFFFFFFu, ((v0 | v1) & 0xFFFFFF00u) != 0u) != 0u;

    // ---- early global prefetches (independent; overlap with everything) ----
    float w2col[IN_CH];
    #pragma unroll
    for (int i = 0; i < IN_CH; i++)
        w2col[i] = w2[h * (IN_CH * OUT_CH) + i * OUT_CH + o];

    int len_pref;  // resolve int32 vs int64 (true lengths >= 1 -> hi word 0 <=> i64)
    {
        const int hw = __ldg(&lengths_i32[1]);
        len_pref = (hw == 0) ? __ldg(&lengths_i32[2 * b]) : __ldg(&lengths_i32[b]);
    }

    int j0 = l_start - (BAND - 1); if (j0 < 0) j0 = 0;
    const int nj = (l_start + TILE_L - 1) - j0 + 1;   // <= NJMAX

    if (t >= 32 && t < 32 + HID) { w1s[t - 32] = w1[t - 32]; b1s[t - 32] = b1[t - 32]; }
    if (t >= 64 && t - 64 < nj)  { ts[t - 64] = times[b * LEN + j0 + (t - 64)]; }
    if (t >= 128 && t < 128 + IN_CH * OUT_CH) b2s[t - 128] = b2[t - 128];

    // feats: unconditional feature load in parallel with mask load, then select
    for (int idx = t; idx < nj * IN_CH; idx += NTHR) {
        const int jr = idx >> 4, i = idx & 15;
        const int j  = j0 + jr;
        const float fv = features[(b * LEN + j) * IN_CH + i];
        bool act;
        if (byte_layout) act = ((const unsigned char*)true_ids_raw)[b * LEN + j] != 0;
        else             act = ((const int*)true_ids_raw)[b * LEN + j] != 0;
        feats[idx] = act ? fv : 0.0f;
    }
    __syncthreads();   // feats, ts, w1s, b2s visible

    // ---- phase 1: FW2 / FB2, rows split 8 ways; FB2 spread across h-warps ----
    {
        const int q = (nj + NGRP - 1) >> 3;
        const int jrA = g * q;
        int jrB = jrA + q; if (jrB > nj) jrB = nj;
        for (int jr = jrA; jr < jrB; jr++) {
            const float* fj = &feats[jr * IN_CH];
            float aA = 0.0f, aB = 0.0f;
            #pragma unroll
            for (int i = 0; i < 8; i++) {
                aA = fmaf(fj[i],     w2col[i],     aA);
                aB = fmaf(fj[i + 8], w2col[i + 8], aB);
            }
            fw2s[jr * FW2_STR + h * OUT_CH + o] = aA + aB;
            if (h == (jr & 7)) {           // one o-row of threads per jr does FB2
                float bA = 0.0f, bB = 0.0f;
                #pragma unroll
                for (int i = 0; i < 8; i++) {
                    bA = fmaf(fj[i],     b2s[i * OUT_CH + o],       bA);
                    bB = fmaf(fj[i + 8], b2s[(i + 8) * OUT_CH + o], bB);
                }
                fw2s[jr * FW2_STR + HID * OUT_CH + o] = bA + bB;
            }
        }
    }
    __syncthreads();

    // ---- phase 2: band reduction per (l, o), band split 8 ways across groups ----
    const int l  = l_start + h;      // h == l_local here
    const int lr = l - j0;
    const float tl = ts[lr];

    float w1r[HID], b1r[HID];
    #pragma unroll
    for (int k = 0; k < HID; k++) { w1r[k] = w1s[k]; b1r[k] = b1s[k]; }

    int jr_lo = lr - (BAND - 1); if (jr_lo < 0) jr_lo = 0;
    const int blen = lr - jr_lo + 1;
    const int q2 = (blen + NGRP - 1) >> 3;
    const int js = jr_lo + g * q2;
    int je = js + q2; if (je > lr + 1) je = lr + 1;

    float acc0 = 0.0f, acc1 = 0.0f;
    for (int jr = js; jr < je; jr++) {
        const float dt = tl - ts[jr];
        const float* fr = &fw2s[jr * FW2_STR];
        float a0 = fr[HID * OUT_CH + o];   // FB2 term
        float a1 = 0.0f;
        #pragma unroll
        for (int k = 0; k < HID; k += 2) {
            float hv0 = fmaf(dt, w1r[k],     b1r[k]);     hv0 = hv0 > 0.0f ? hv0 : 0.0f;
            float hv1 = fmaf(dt, w1r[k + 1], b1r[k + 1]); hv1 = hv1 > 0.0f ? hv1 : 0.0f;
            a0 = fmaf(hv0, fr[k * OUT_CH + o],       a0);
            a1 = fmaf(hv1, fr[(k + 1) * OUT_CH + o], a1);
        }
        acc0 += a0; acc1 += a1;
    }
    float acc = acc0 + acc1;

    if (g > 0) partial[(g - 1) * 128 + m] = acc;
    __syncthreads();

    if (g == 0) {
        float p0 = partial[m]           + partial[128 + m];
        float p1 = partial[2 * 128 + m] + partial[3 * 128 + m];
        float p2 = partial[4 * 128 + m] + partial[5 * 128 + m];
        acc += (p0 + p1) + (p2 + partial[6 * 128 + m]);
        const bool valid = l <= 6 * (len_pref - 1);
        out[(b * LEN + l) * OUT_CH + o] = valid ? acc : 0.0f;
    }
}

extern "C" void kernel_launch(void* const* d_in, const int* in_sizes, int n_in,
                              void* d_out, int out_size) {
    using namespace cc;
    // dict order: times, features, lengths, true_ids, [sim_size], w1, b1, w2, b2
    const float* times    = (const float*)d_in[0];
    const float* features = (const float*)d_in[1];
    const int*   lengths  = (const int*)d_in[2];
    const void*  tids     = d_in[3];

    int base = 4;
    if (n_in >= 9 && in_sizes[4] == 1) base = 5;  // sim_size scalar occupies slot 4

    const float* w1 = (const float*)d_in[base + 0];
    const float* b1 = (const float*)d_in[base + 1];
    const float* w2 = (const float*)d_in[base + 2];
    const float* b2 = (const float*)d_in[base + 3];
    float*       out = (float*)d_out;

    dim3 grid(LEN / TILE_L, BSZ);   // 64 x 2 = 128 blocks, 1 per SM
    cc1d_fused_kernel<<<grid, NTHR>>>(times, features, lengths, tids,
                                      w1, b1, w2, b2, out);
}

// round 7
// speedup vs baseline: 1.0775x; 1.0295x over previous
#include <cuda_runtime.h>

// ContConv1dDenseSim: out[b,l,o] = sum_{j in band, i} feat[b,j,i] * kv(dt_{l,j})[i,o]
// kv = MLP(relu) on scalar dt; banded causal mask (width 30); true_ids column mask;
// row-validity l <= 6*(len-1).
//
// Refactor (exact): FW2[j,h,o] = sum_i feat[j,i]*w2[h,i*16+o]; FB2[j,o] = sum_i feat[j,i]*b2[i*16+o]
// out[l,o] = sum_{j in band} ( FB2[j,o] + sum_h relu(dt*w1_h + b1_h) * FW2[j,h,o] )
//
// R7: instruction-count attack. fw2s transposed to [jr][o][12] (h innermost,
// padded for float4): phase-2 inner = 2x LDS.128 + 1x LDS.32 instead of 9 scalar
// LDS. Phase-1 feats rows read as float4 (broadcast). feats fill via float4.

namespace cc {
constexpr int LEN     = 512;
constexpr int BSZ     = 2;
constexpr int IN_CH   = 16;
constexpr int OUT_CH  = 16;
constexpr int HID     = 8;
constexpr int BAND    = 30;                 // j in [l-29, l]
constexpr int TILE_L  = 8;
constexpr int NJMAX   = BAND - 1 + TILE_L;  // 37
constexpr int OSTR    = 12;                 // per-o slot: 8 FW2 + FB2 + pad (16B aligned)
constexpr int JSTR    = OUT_CH * OSTR;      // 192 floats per jr row
constexpr int NTHR    = 1024;
constexpr int NGRP    = 8;
}

__global__ __launch_bounds__(1024, 1)
void cc1d_fused_kernel(const float* __restrict__ times,
                       const float* __restrict__ features,
                       const int* __restrict__ lengths_i32,   // int32 or int64 layout
                       const void* __restrict__ true_ids_raw, // u8 or int32 layout
                       const float* __restrict__ w1,
                       const float* __restrict__ b1,
                       const float* __restrict__ w2,
                       const float* __restrict__ b2,
                       float* __restrict__ out)
{
    using namespace cc;
    __shared__ __align__(16) float feats[NJMAX * IN_CH];
    __shared__ __align__(16) float fw2s[NJMAX * JSTR];
    __shared__ float ts[NJMAX];
    __shared__ float w1s[HID], b1s[HID];
    __shared__ float b2s[IN_CH * OUT_CH];      // [i*16+o]
    __shared__ float partial[(NGRP - 1) * 128];

    const int b       = blockIdx.y;
    const int l_start = blockIdx.x * TILE_L;
    const int t       = threadIdx.x;
    const int g       = t >> 7;         // work-split group 0..7
    const int m       = t & 127;
    const int h       = m >> 4;         // hidden unit (phase1) / l_local (phase2)
    const int o       = m & 15;
    const int lane    = t & 31;

    // ---- per-warp true_ids layout detection: every warp scans the same first
    // 256 bytes (L1-resident after first touch). int32-bool values are 0/1, so
    // any nonzero byte above byte-0 => 1-byte layout. No shared mem, no sync.
    unsigned int v0 = ((const unsigned int*)true_ids_raw)[lane];
    unsigned int v1 = ((const unsigned int*)true_ids_raw)[lane + 32];
    const bool byte_layout =
        __ballot_sync(0xFFFFFFFFu, ((v0 | v1) & 0xFFFFFF00u) != 0u) != 0u;

    // ---- early global prefetches (independent; overlap with everything) ----
    float w2col[IN_CH];
    #pragma unroll
    for (int i = 0; i < IN_CH; i++)
        w2col[i] = w2[h * (IN_CH * OUT_CH) + i * OUT_CH + o];

    int len_pref;  // resolve int32 vs int64 (true lengths >= 1 -> hi word 0 <=> i64)
    {
        const int hw = __ldg(&lengths_i32[1]);
        len_pref = (hw == 0) ? __ldg(&lengths_i32[2 * b]) : __ldg(&lengths_i32[b]);
    }

    int j0 = l_start - (BAND - 1); if (j0 < 0) j0 = 0;
    const int nj = (l_start + TILE_L - 1) - j0 + 1;   // <= NJMAX

    if (t >= 32 && t < 32 + HID) { w1s[t - 32] = w1[t - 32]; b1s[t - 32] = b1[t - 32]; }
    if (t >= 64 && t - 64 < nj)  { ts[t - 64] = times[b * LEN + j0 + (t - 64)]; }
    if (t >= 128 && t < 128 + IN_CH * OUT_CH) b2s[t - 128] = b2[t - 128];

    // feats fill: float4 feature load in parallel with mask load, then select
    {
        float4* feats4 = (float4*)feats;
        const float4* gfeat4 = (const float4*)features;
        for (int idx = t; idx < nj * 4; idx += NTHR) {
            const int jr = idx >> 2;
            const int j  = j0 + jr;
            float4 fv = gfeat4[(b * LEN + j) * 4 + (idx & 3)];
            bool act;
            if (byte_layout) act = ((const unsigned char*)true_ids_raw)[b * LEN + j] != 0;
            else             act = ((const int*)true_ids_raw)[b * LEN + j] != 0;
            if (!act) fv = make_float4(0.f, 0.f, 0.f, 0.f);
            feats4[idx] = fv;
        }
    }
    __syncthreads();   // feats, ts, w1s, b2s visible

    // ---- phase 1: FW2/FB2 transposed store, rows split 8 ways ----
    {
        const int q = (nj + NGRP - 1) >> 3;
        const int jrA = g * q;
        int jrB = jrA + q; if (jrB > nj) jrB = nj;
        for (int jr = jrA; jr < jrB; jr++) {
            const float4* fj4 = (const float4*)&feats[jr * IN_CH];
            float4 fa = fj4[0], fb = fj4[1];
            float aA = 0.0f, aB = 0.0f;
            aA = fmaf(fa.x, w2col[0], aA); aB = fmaf(fb.x, w2col[4], aB);
            aA = fmaf(fa.y, w2col[1], aA); aB = fmaf(fb.y, w2col[5], aB);
            aA = fmaf(fa.z, w2col[2], aA); aB = fmaf(fb.z, w2col[6], aB);
            aA = fmaf(fa.w, w2col[3], aA); aB = fmaf(fb.w, w2col[7], aB);
            float4 fc = fj4[2], fd = fj4[3];
            aA = fmaf(fc.x, w2col[8],  aA); aB = fmaf(fd.x, w2col[12], aB);
            aA = fmaf(fc.y, w2col[9],  aA); aB = fmaf(fd.y, w2col[13], aB);
            aA = fmaf(fc.z, w2col[10], aA); aB = fmaf(fd.z, w2col[14], aB);
            aA = fmaf(fc.w, w2col[11], aA); aB = fmaf(fd.w, w2col[15], aB);
            fw2s[jr * JSTR + o * OSTR + h] = aA + aB;
            if (h == (jr & 7)) {           // one o-row of threads per jr does FB2
                float bA = 0.0f, bB = 0.0f;
                bA = fmaf(fa.x, b2s[0 * 16 + o],  bA); bB = fmaf(fb.x, b2s[4 * 16 + o],  bB);
                bA = fmaf(fa.y, b2s[1 * 16 + o],  bA); bB = fmaf(fb.y, b2s[5 * 16 + o],  bB);
                bA = fmaf(fa.z, b2s[2 * 16 + o],  bA); bB = fmaf(fb.z, b2s[6 * 16 + o],  bB);
                bA = fmaf(fa.w, b2s[3 * 16 + o],  bA); bB = fmaf(fb.w, b2s[7 * 16 + o],  bB);
                bA = fmaf(fc.x, b2s[8 * 16 + o],  bA); bB = fmaf(fd.x, b2s[12 * 16 + o], bB);
                bA = fmaf(fc.y, b2s[9 * 16 + o],  bA); bB = fmaf(fd.y, b2s[13 * 16 + o], bB);
                bA = fmaf(fc.z, b2s[10 * 16 + o], bA); bB = fmaf(fd.z, b2s[14 * 16 + o], bB);
                bA = fmaf(fc.w, b2s[11 * 16 + o], bA); bB = fmaf(fd.w, b2s[15 * 16 + o], bB);
                fw2s[jr * JSTR + o * OSTR + 8] = bA + bB;
            }
        }
    }
    __syncthreads();

    // ---- phase 2: band reduction per (l, o), band split 8 ways across groups ----
    const int l  = l_start + h;      // h == l_local here
    const int lr = l - j0;
    const float tl = ts[lr];

    float w1r[HID], b1r[HID];
    #pragma unroll
    for (int k = 0; k < HID; k++) { w1r[k] = w1s[k]; b1r[k] = b1s[k]; }

    int jr_lo = lr - (BAND - 1); if (jr_lo < 0) jr_lo = 0;
    const int blen = lr - jr_lo + 1;
    const int q2 = (blen + NGRP - 1) >> 3;
    const int js = jr_lo + g * q2;
    int je = js + q2; if (je > lr + 1) je = lr + 1;

    float acc0 = 0.0f, acc1 = 0.0f;
    for (int jr = js; jr < je; jr++) {
        const float dt = tl - ts[jr];
        const float* frp = &fw2s[jr * JSTR + o * OSTR];
        const float4 fA = *(const float4*)frp;        // FW2 h=0..3
        const float4 fB = *(const float4*)(frp + 4);  // FW2 h=4..7
        float a0 = frp[8];                            // FB2 term
        float a1 = 0.0f;
        float hv;
        hv = fmaf(dt, w1r[0], b1r[0]); hv = hv > 0.f ? hv : 0.f; a0 = fmaf(hv, fA.x, a0);
        hv = fmaf(dt, w1r[1], b1r[1]); hv = hv > 0.f ? hv : 0.f; a1 = fmaf(hv, fA.y, a1);
        hv = fmaf(dt, w1r[2], b1r[2]); hv = hv > 0.f ? hv : 0.f; a0 = fmaf(hv, fA.z, a0);
        hv = fmaf(dt, w1r[3], b1r[3]); hv = hv > 0.f ? hv : 0.f; a1 = fmaf(hv, fA.w, a1);
        hv = fmaf(dt, w1r[4], b1r[4]); hv = hv > 0.f ? hv : 0.f; a0 = fmaf(hv, fB.x, a0);
        hv = fmaf(dt, w1r[5], b1r[5]); hv = hv > 0.f ? hv : 0.f; a1 = fmaf(hv, fB.y, a1);
        hv = fmaf(dt, w1r[6], b1r[6]); hv = hv > 0.f ? hv : 0.f; a0 = fmaf(hv, fB.z, a0);
        hv = fmaf(dt, w1r[7], b1r[7]); hv = hv > 0.f ? hv : 0.f; a1 = fmaf(hv, fB.w, a1);
        acc0 += a0; acc1 += a1;
    }
    float acc = acc0 + acc1;

    if (g > 0) partial[(g - 1) * 128 + m] = acc;
    __syncthreads();

    if (g == 0) {
        float p0 = partial[m]           + partial[128 + m];
        float p1 = partial[2 * 128 + m] + partial[3 * 128 + m];
        float p2 = partial[4 * 128 + m] + partial[5 * 128 + m];
        acc += (p0 + p1) + (p2 + partial[6 * 128 + m]);
        const bool valid = l <= 6 * (len_pref - 1);
        out[(b * LEN + l) * OUT_CH + o] = valid ? acc : 0.0f;
    }
}

extern "C" void kernel_launch(void* const* d_in, const int* in_sizes, int n_in,
                              void* d_out, int out_size) {
    using namespace cc;
    // dict order: times, features, lengths, true_ids, [sim_size], w1, b1, w2, b2
    const float* times    = (const float*)d_in[0];
    const float* features = (const float*)d_in[1];
    const int*   lengths  = (const int*)d_in[2];
    const void*  tids     = d_in[3];

    int base = 4;
    if (n_in >= 9 && in_sizes[4] == 1) base = 5;  // sim_size scalar occupies slot 4

    const float* w1 = (const float*)d_in[base + 0];
    const float* b1 = (const float*)d_in[base + 1];
    const float* w2 = (const float*)d_in[base + 2];
    const float* b2 = (const float*)d_in[base + 3];
    float*       out = (float*)d_out;

    dim3 grid(LEN / TILE_L, BSZ);   // 64 x 2 = 128 blocks, 1 per SM
    cc1d_fused_kernel<<<grid, NTHR>>>(times, features, lengths, tids,
                                      w1, b1, w2, b2, out);
}